// round 5
// baseline (speedup 1.0000x reference)
#include <cuda_runtime.h>
#include <cuda_fp16.h>
#include <cstdint>

#define BATCH     4
#define NHEAD     16
#define SEQ       2048
#define DHEAD     64
#define ROWSTRIDE 3072
#define NSTATE    1024
#define BM        128
#define BN        64
#define NTHREADS  128
#define KPAD      72

__device__ __forceinline__ uint32_t h2pack(float lo, float hi) {
    __half2 h = __floats2half2_rn(lo, hi);
    return *reinterpret_cast<uint32_t*>(&h);
}

__device__ __forceinline__ void split2(float fx, float fy, uint32_t& hi, uint32_t& lo) {
    __half hx = __float2half_rn(fx);
    __half hy = __float2half_rn(fy);
    __half2 hh = __halves2half2(hx, hy);
    hi = *reinterpret_cast<uint32_t*>(&hh);
    lo = h2pack(fx - __half2float(hx), fy - __half2float(hy));
}

__device__ __forceinline__ void mma16816(float* c, const uint32_t* a, uint32_t b0, uint32_t b1) {
    asm volatile(
        "mma.sync.aligned.m16n8k16.row.col.f32.f16.f16.f32 "
        "{%0,%1,%2,%3}, {%4,%5,%6,%7}, {%8,%9}, {%0,%1,%2,%3};"
        : "+f"(c[0]), "+f"(c[1]), "+f"(c[2]), "+f"(c[3])
        : "r"(a[0]), "r"(a[1]), "r"(a[2]), "r"(a[3]), "r"(b0), "r"(b1));
}

__device__ __forceinline__ void ldsm_x4(uint32_t& r0, uint32_t& r1, uint32_t& r2, uint32_t& r3,
                                        uint32_t addr) {
    asm volatile("ldmatrix.sync.aligned.m8n8.x4.shared.b16 {%0,%1,%2,%3}, [%4];"
                 : "=r"(r0), "=r"(r1), "=r"(r2), "=r"(r3) : "r"(addr));
}

__device__ __forceinline__ void ldsm_x4_t(uint32_t& r0, uint32_t& r1, uint32_t& r2, uint32_t& r3,
                                          uint32_t addr) {
    asm volatile("ldmatrix.sync.aligned.m8n8.x4.trans.shared.b16 {%0,%1,%2,%3}, [%4];"
                 : "=r"(r0), "=r"(r1), "=r"(r2), "=r"(r3) : "r"(addr));
}

__global__ __launch_bounds__(NTHREADS, 2)
void fa_kernel(const float* __restrict__ x, float* __restrict__ out) {
    __shared__ alignas(16) __half Kh[BN][KPAD];
    __shared__ alignas(16) __half Kl[BN][KPAD];
    __shared__ alignas(16) __half Vh[BN][KPAD];
    __shared__ alignas(16) __half Vl[BN][KPAD];

    const int qtile = blockIdx.x;
    const int h     = blockIdx.y;
    const int b     = blockIdx.z;
    const int tid   = threadIdx.x;
    const int lane  = tid & 31;
    const int warp  = tid >> 5;
    const int g     = lane >> 2;
    const int qr    = lane & 3;

    const size_t base = (size_t)b * SEQ * ROWSTRIDE + (size_t)h * DHEAD;
    const int rowA = qtile * BM + warp * 32 + g;

    const int r8 = lane & 7;
    const int krow = (((lane >> 4) & 1) << 3) + r8;
    const int kcol = ((lane >> 3) & 1) << 3;
    const int vrow = (((lane >> 3) & 1) << 3) + r8;
    const int vcol = ((lane >> 4) & 1) << 3;

    const uint32_t aKh = (uint32_t)__cvta_generic_to_shared(&Kh[krow][kcol]);
    const uint32_t aKl = (uint32_t)__cvta_generic_to_shared(&Kl[krow][kcol]);
    const uint32_t aVh = (uint32_t)__cvta_generic_to_shared(&Vh[vrow][vcol]);
    const uint32_t aVl = (uint32_t)__cvta_generic_to_shared(&Vl[vrow][vcol]);

    // ---- Q fragments for both M-tiles ----
    uint32_t qh[2][4][4], ql[2][4][4];
#pragma unroll
    for (int mt = 0; mt < 2; mt++) {
        const int r0 = rowA + mt * 16;
#pragma unroll
        for (int ks = 0; ks < 4; ks++) {
            const int c = ks * 16 + qr * 2;
            const float* p0 = x + base + (size_t)r0 * ROWSTRIDE + c;
            const float* p1 = x + base + (size_t)(r0 + 8) * ROWSTRIDE + c;
            float2 f0 = *reinterpret_cast<const float2*>(p0);
            float2 f1 = *reinterpret_cast<const float2*>(p1);
            float2 f2 = *reinterpret_cast<const float2*>(p0 + 8);
            float2 f3 = *reinterpret_cast<const float2*>(p1 + 8);
            split2(f0.x, f0.y, qh[mt][ks][0], ql[mt][ks][0]);
            split2(f1.x, f1.y, qh[mt][ks][1], ql[mt][ks][1]);
            split2(f2.x, f2.y, qh[mt][ks][2], ql[mt][ks][2]);
            split2(f3.x, f3.y, qh[mt][ks][3], ql[mt][ks][3]);
        }
    }

    float o[2][8][4];
#pragma unroll
    for (int mt = 0; mt < 2; mt++)
#pragma unroll
        for (int nd = 0; nd < 8; nd++)
#pragma unroll
            for (int e = 0; e < 4; e++) o[mt][nd][e] = 0.f;

    float m[2]  = {-INFINITY, -INFINITY};   // shared max per 2-row pair (exact: max of both rows)
    float l0[2] = {0.f, 0.f};               // row g sum
    float l1[2] = {0.f, 0.f};               // row g+8 sum

    const int njt = 2 * qtile + 2;

    for (int j = 0; j < njt; j++) {
        const int kb = j * BN;
#pragma unroll
        for (int i = 0; i < 8; i++) {
            const int fi = i * NTHREADS + tid;
            const int r  = fi >> 4;
            const int c4 = (fi & 15) << 2;
            const float* rowp = x + base + (size_t)(kb + r) * ROWSTRIDE;
            float4 kv = *reinterpret_cast<const float4*>(rowp + NSTATE + c4);
            float4 vv = *reinterpret_cast<const float4*>(rowp + 2 * NSTATE + c4);

            __half2 kh01 = __floats2half2_rn(kv.x, kv.y);
            __half2 kh23 = __floats2half2_rn(kv.z, kv.w);
            float2 kb01 = __half22float2(kh01);
            float2 kb23 = __half22float2(kh23);
            __half2 kl01 = __floats2half2_rn(kv.x - kb01.x, kv.y - kb01.y);
            __half2 kl23 = __floats2half2_rn(kv.z - kb23.x, kv.w - kb23.y);

            __half2 vh01 = __floats2half2_rn(vv.x, vv.y);
            __half2 vh23 = __floats2half2_rn(vv.z, vv.w);
            float2 vb01 = __half22float2(vh01);
            float2 vb23 = __half22float2(vh23);
            __half2 vl01 = __floats2half2_rn(vv.x - vb01.x, vv.y - vb01.y);
            __half2 vl23 = __floats2half2_rn(vv.z - vb23.x, vv.w - vb23.y);

            uint2 pk_h = {*reinterpret_cast<uint32_t*>(&kh01), *reinterpret_cast<uint32_t*>(&kh23)};
            uint2 pk_l = {*reinterpret_cast<uint32_t*>(&kl01), *reinterpret_cast<uint32_t*>(&kl23)};
            uint2 pv_h = {*reinterpret_cast<uint32_t*>(&vh01), *reinterpret_cast<uint32_t*>(&vh23)};
            uint2 pv_l = {*reinterpret_cast<uint32_t*>(&vl01), *reinterpret_cast<uint32_t*>(&vl23)};
            *reinterpret_cast<uint2*>(&Kh[r][c4]) = pk_h;
            *reinterpret_cast<uint2*>(&Kl[r][c4]) = pk_l;
            *reinterpret_cast<uint2*>(&Vh[r][c4]) = pv_h;
            *reinterpret_cast<uint2*>(&Vl[r][c4]) = pv_l;
        }
        __syncthreads();

        float s[2][8][4];
#pragma unroll
        for (int mt = 0; mt < 2; mt++)
#pragma unroll
            for (int nt = 0; nt < 8; nt++)
#pragma unroll
                for (int e = 0; e < 4; e++) s[mt][nt][e] = 0.f;

#pragma unroll
        for (int ks = 0; ks < 4; ks++) {
#pragma unroll
            for (int ntp = 0; ntp < 4; ntp++) {
                const int nt = ntp * 2;
                const uint32_t off = (uint32_t)((nt * 8 * KPAD + ks * 16) * 2);
                uint32_t bh0, bh1, bh2, bh3, bl0, bl1, bl2, bl3;
                ldsm_x4(bh0, bh1, bh2, bh3, aKh + off);
                ldsm_x4(bl0, bl1, bl2, bl3, aKl + off);
#pragma unroll
                for (int mt = 0; mt < 2; mt++) {
                    mma16816(s[mt][nt],     qh[mt][ks], bh0, bh1);
                    mma16816(s[mt][nt],     ql[mt][ks], bh0, bh1);
                    mma16816(s[mt][nt],     qh[mt][ks], bl0, bl1);
                    mma16816(s[mt][nt + 1], qh[mt][ks], bh2, bh3);
                    mma16816(s[mt][nt + 1], ql[mt][ks], bh2, bh3);
                    mma16816(s[mt][nt + 1], qh[mt][ks], bl2, bl3);
                }
            }
        }

#pragma unroll
        for (int mt = 0; mt < 2; mt++) {
            const int tmin = qtile * BM + warp * 32 + mt * 16;
            const int grl0 = tmin + g;
            const int grl1 = grl0 + 8;
#pragma unroll
            for (int nt = 0; nt < 8; nt++)
#pragma unroll
                for (int e = 0; e < 4; e++) s[mt][nt][e] *= 0.125f;
            if (kb + BN - 1 > tmin) {
#pragma unroll
                for (int nt = 0; nt < 8; nt++) {
                    const int kg = kb + nt * 8 + qr * 2;
                    if (kg     > grl0) s[mt][nt][0] = -1e30f;
                    if (kg + 1 > grl0) s[mt][nt][1] = -1e30f;
                    if (kg     > grl1) s[mt][nt][2] = -1e30f;
                    if (kg + 1 > grl1) s[mt][nt][3] = -1e30f;
                }
            }

            float mx = -INFINITY;
#pragma unroll
            for (int nt = 0; nt < 8; nt++) {
                mx = fmaxf(mx, fmaxf(s[mt][nt][0], s[mt][nt][1]));
                mx = fmaxf(mx, fmaxf(s[mt][nt][2], s[mt][nt][3]));
            }
            mx = fmaxf(mx, __shfl_xor_sync(0xffffffffu, mx, 1));
            mx = fmaxf(mx, __shfl_xor_sync(0xffffffffu, mx, 2));

            const float mn = fmaxf(m[mt], mx);
            const float a  = __expf(m[mt] - mn);
            m[mt] = mn;

            float sum0 = 0.f, sum1 = 0.f;
#pragma unroll
            for (int nt = 0; nt < 8; nt++) {
                s[mt][nt][0] = __expf(s[mt][nt][0] - mn); sum0 += s[mt][nt][0];
                s[mt][nt][1] = __expf(s[mt][nt][1] - mn); sum0 += s[mt][nt][1];
                s[mt][nt][2] = __expf(s[mt][nt][2] - mn); sum1 += s[mt][nt][2];
                s[mt][nt][3] = __expf(s[mt][nt][3] - mn); sum1 += s[mt][nt][3];
            }
            sum0 += __shfl_xor_sync(0xffffffffu, sum0, 1);
            sum0 += __shfl_xor_sync(0xffffffffu, sum0, 2);
            sum1 += __shfl_xor_sync(0xffffffffu, sum1, 1);
            sum1 += __shfl_xor_sync(0xffffffffu, sum1, 2);
            l0[mt] = l0[mt] * a + sum0;
            l1[mt] = l1[mt] * a + sum1;

#pragma unroll
            for (int nd = 0; nd < 8; nd++) {
                o[mt][nd][0] *= a; o[mt][nd][1] *= a;
                o[mt][nd][2] *= a; o[mt][nd][3] *= a;
            }
        }

#pragma unroll
        for (int ks2 = 0; ks2 < 4; ks2++) {
            const int n2 = ks2 * 2;
            uint32_t pah[2][4], pal[2][4];
#pragma unroll
            for (int mt = 0; mt < 2; mt++) {
                split2(s[mt][n2][0],     s[mt][n2][1],     pah[mt][0], pal[mt][0]);
                split2(s[mt][n2][2],     s[mt][n2][3],     pah[mt][1], pal[mt][1]);
                split2(s[mt][n2 + 1][0], s[mt][n2 + 1][1], pah[mt][2], pal[mt][2]);
                split2(s[mt][n2 + 1][2], s[mt][n2 + 1][3], pah[mt][3], pal[mt][3]);
            }
#pragma unroll
            for (int ndp = 0; ndp < 4; ndp++) {
                const int nd = ndp * 2;
                const uint32_t off = (uint32_t)((ks2 * 16 * KPAD + nd * 8) * 2);
                uint32_t bh0, bh1, bh2, bh3, bl0, bl1, bl2, bl3;
                ldsm_x4_t(bh0, bh1, bh2, bh3, aVh + off);
                ldsm_x4_t(bl0, bl1, bl2, bl3, aVl + off);
#pragma unroll
                for (int mt = 0; mt < 2; mt++) {
                    mma16816(o[mt][nd],     pah[mt], bh0, bh1);
                    mma16816(o[mt][nd],     pal[mt], bh0, bh1);
                    mma16816(o[mt][nd],     pah[mt], bl0, bl1);
                    mma16816(o[mt][nd + 1], pah[mt], bh2, bh3);
                    mma16816(o[mt][nd + 1], pal[mt], bh2, bh3);
                    mma16816(o[mt][nd + 1], pah[mt], bl2, bl3);
                }
            }
        }
        __syncthreads();
    }

    float* ob = out + (size_t)b * SEQ * NSTATE + (size_t)h * DHEAD;
#pragma unroll
    for (int mt = 0; mt < 2; mt++) {
        const int r0 = rowA + mt * 16;
        const float inv0 = 1.f / l0[mt];
        const float inv1 = 1.f / l1[mt];
#pragma unroll
        for (int nd = 0; nd < 8; nd++) {
            const int dcol = nd * 8 + qr * 2;
            float2 v0; v0.x = o[mt][nd][0] * inv0; v0.y = o[mt][nd][1] * inv0;
            float2 v1; v1.x = o[mt][nd][2] * inv1; v1.y = o[mt][nd][3] * inv1;
            *reinterpret_cast<float2*>(ob + (size_t)r0 * NSTATE + dcol) = v0;
            *reinterpret_cast<float2*>(ob + (size_t)(r0 + 8) * NSTATE + dcol) = v1;
        }
    }
}

extern "C" void kernel_launch(void* const* d_in, const int* in_sizes, int n_in,
                              void* d_out, int out_size) {
    const float* x = (const float*)d_in[0];
    float* out = (float*)d_out;
    dim3 grid(SEQ / BM, NHEAD, BATCH);
    fa_kernel<<<grid, NTHREADS>>>(x, out);
}

// round 6
// speedup vs baseline: 1.0098x; 1.0098x over previous
#include <cuda_runtime.h>
#include <cuda_fp16.h>
#include <cstdint>

#define BATCH     4
#define NHEAD     16
#define SEQ       2048
#define DHEAD     64
#define ROWSTRIDE 3072
#define NSTATE    1024
#define BM        128
#define BN        64
#define NTHREADS  128
#define KPAD      72

__device__ __forceinline__ uint32_t h2pack(float lo, float hi) {
    __half2 h = __floats2half2_rn(lo, hi);
    return *reinterpret_cast<uint32_t*>(&h);
}

__device__ __forceinline__ void split2(float fx, float fy, uint32_t& hi, uint32_t& lo) {
    __half hx = __float2half_rn(fx);
    __half hy = __float2half_rn(fy);
    __half2 hh = __halves2half2(hx, hy);
    hi = *reinterpret_cast<uint32_t*>(&hh);
    lo = h2pack(fx - __half2float(hx), fy - __half2float(hy));
}

__device__ __forceinline__ void mma16816(float* c, const uint32_t* a, uint32_t b0, uint32_t b1) {
    asm volatile(
        "mma.sync.aligned.m16n8k16.row.col.f32.f16.f16.f32 "
        "{%0,%1,%2,%3}, {%4,%5,%6,%7}, {%8,%9}, {%0,%1,%2,%3};"
        : "+f"(c[0]), "+f"(c[1]), "+f"(c[2]), "+f"(c[3])
        : "r"(a[0]), "r"(a[1]), "r"(a[2]), "r"(a[3]), "r"(b0), "r"(b1));
}

__device__ __forceinline__ void ldsm_x4(uint32_t& r0, uint32_t& r1, uint32_t& r2, uint32_t& r3,
                                        uint32_t addr) {
    asm volatile("ldmatrix.sync.aligned.m8n8.x4.shared.b16 {%0,%1,%2,%3}, [%4];"
                 : "=r"(r0), "=r"(r1), "=r"(r2), "=r"(r3) : "r"(addr));
}

__device__ __forceinline__ void ldsm_x4_t(uint32_t& r0, uint32_t& r1, uint32_t& r2, uint32_t& r3,
                                          uint32_t addr) {
    asm volatile("ldmatrix.sync.aligned.m8n8.x4.trans.shared.b16 {%0,%1,%2,%3}, [%4];"
                 : "=r"(r0), "=r"(r1), "=r"(r2), "=r"(r3) : "r"(addr));
}

__global__ __launch_bounds__(NTHREADS, 2)
void fa_kernel(const float* __restrict__ x, float* __restrict__ out) {
    __shared__ alignas(16) __half Kh[BN][KPAD];
    __shared__ alignas(16) __half Kl[BN][KPAD];
    __shared__ alignas(16) __half Vh[BN][KPAD];
    __shared__ alignas(16) __half Vl[BN][KPAD];

    const int qtile = blockIdx.x;
    const int h     = blockIdx.y;
    const int b     = blockIdx.z;
    const int tid   = threadIdx.x;
    const int lane  = tid & 31;
    const int warp  = tid >> 5;
    const int g     = lane >> 2;
    const int qr    = lane & 3;

    const size_t base = (size_t)b * SEQ * ROWSTRIDE + (size_t)h * DHEAD;
    const int rowA = qtile * BM + warp * 32 + g;

    const int r8 = lane & 7;
    const int krow = (((lane >> 4) & 1) << 3) + r8;
    const int kcol = ((lane >> 3) & 1) << 3;
    const int vrow = (((lane >> 3) & 1) << 3) + r8;
    const int vcol = ((lane >> 4) & 1) << 3;

    const uint32_t aKh = (uint32_t)__cvta_generic_to_shared(&Kh[krow][kcol]);
    const uint32_t aKl = (uint32_t)__cvta_generic_to_shared(&Kl[krow][kcol]);
    const uint32_t aVh = (uint32_t)__cvta_generic_to_shared(&Vh[vrow][vcol]);
    const uint32_t aVl = (uint32_t)__cvta_generic_to_shared(&Vl[vrow][vcol]);

    // ---- Q fragments for both M-tiles ----
    uint32_t qh[2][4][4], ql[2][4][4];
#pragma unroll
    for (int mt = 0; mt < 2; mt++) {
        const int r0 = rowA + mt * 16;
#pragma unroll
        for (int ks = 0; ks < 4; ks++) {
            const int c = ks * 16 + qr * 2;
            const float* p0 = x + base + (size_t)r0 * ROWSTRIDE + c;
            const float* p1 = x + base + (size_t)(r0 + 8) * ROWSTRIDE + c;
            float2 f0 = *reinterpret_cast<const float2*>(p0);
            float2 f1 = *reinterpret_cast<const float2*>(p1);
            float2 f2 = *reinterpret_cast<const float2*>(p0 + 8);
            float2 f3 = *reinterpret_cast<const float2*>(p1 + 8);
            split2(f0.x, f0.y, qh[mt][ks][0], ql[mt][ks][0]);
            split2(f1.x, f1.y, qh[mt][ks][1], ql[mt][ks][1]);
            split2(f2.x, f2.y, qh[mt][ks][2], ql[mt][ks][2]);
            split2(f3.x, f3.y, qh[mt][ks][3], ql[mt][ks][3]);
        }
    }

    float o[2][8][4];
#pragma unroll
    for (int mt = 0; mt < 2; mt++)
#pragma unroll
        for (int nd = 0; nd < 8; nd++)
#pragma unroll
            for (int e = 0; e < 4; e++) o[mt][nd][e] = 0.f;

    float m[2]  = {-INFINITY, -INFINITY};   // shared max per 2-row pair (exact: max of both rows)
    float l0[2] = {0.f, 0.f};               // row g sum
    float l1[2] = {0.f, 0.f};               // row g+8 sum

    const int njt = 2 * qtile + 2;

    for (int j = 0; j < njt; j++) {
        const int kb = j * BN;
#pragma unroll
        for (int i = 0; i < 8; i++) {
            const int fi = i * NTHREADS + tid;
            const int r  = fi >> 4;
            const int c4 = (fi & 15) << 2;
            const float* rowp = x + base + (size_t)(kb + r) * ROWSTRIDE;
            float4 kv = *reinterpret_cast<const float4*>(rowp + NSTATE + c4);
            float4 vv = *reinterpret_cast<const float4*>(rowp + 2 * NSTATE + c4);

            __half2 kh01 = __floats2half2_rn(kv.x, kv.y);
            __half2 kh23 = __floats2half2_rn(kv.z, kv.w);
            float2 kb01 = __half22float2(kh01);
            float2 kb23 = __half22float2(kh23);
            __half2 kl01 = __floats2half2_rn(kv.x - kb01.x, kv.y - kb01.y);
            __half2 kl23 = __floats2half2_rn(kv.z - kb23.x, kv.w - kb23.y);

            __half2 vh01 = __floats2half2_rn(vv.x, vv.y);
            __half2 vh23 = __floats2half2_rn(vv.z, vv.w);
            float2 vb01 = __half22float2(vh01);
            float2 vb23 = __half22float2(vh23);
            __half2 vl01 = __floats2half2_rn(vv.x - vb01.x, vv.y - vb01.y);
            __half2 vl23 = __floats2half2_rn(vv.z - vb23.x, vv.w - vb23.y);

            uint2 pk_h = {*reinterpret_cast<uint32_t*>(&kh01), *reinterpret_cast<uint32_t*>(&kh23)};
            uint2 pk_l = {*reinterpret_cast<uint32_t*>(&kl01), *reinterpret_cast<uint32_t*>(&kl23)};
            uint2 pv_h = {*reinterpret_cast<uint32_t*>(&vh01), *reinterpret_cast<uint32_t*>(&vh23)};
            uint2 pv_l = {*reinterpret_cast<uint32_t*>(&vl01), *reinterpret_cast<uint32_t*>(&vl23)};
            *reinterpret_cast<uint2*>(&Kh[r][c4]) = pk_h;
            *reinterpret_cast<uint2*>(&Kl[r][c4]) = pk_l;
            *reinterpret_cast<uint2*>(&Vh[r][c4]) = pv_h;
            *reinterpret_cast<uint2*>(&Vl[r][c4]) = pv_l;
        }
        __syncthreads();

        float s[2][8][4];
#pragma unroll
        for (int mt = 0; mt < 2; mt++)
#pragma unroll
            for (int nt = 0; nt < 8; nt++)
#pragma unroll
                for (int e = 0; e < 4; e++) s[mt][nt][e] = 0.f;

#pragma unroll
        for (int ks = 0; ks < 4; ks++) {
#pragma unroll
            for (int ntp = 0; ntp < 4; ntp++) {
                const int nt = ntp * 2;
                const uint32_t off = (uint32_t)((nt * 8 * KPAD + ks * 16) * 2);
                uint32_t bh0, bh1, bh2, bh3, bl0, bl1, bl2, bl3;
                ldsm_x4(bh0, bh1, bh2, bh3, aKh + off);
                ldsm_x4(bl0, bl1, bl2, bl3, aKl + off);
#pragma unroll
                for (int mt = 0; mt < 2; mt++) {
                    mma16816(s[mt][nt],     qh[mt][ks], bh0, bh1);
                    mma16816(s[mt][nt],     ql[mt][ks], bh0, bh1);
                    mma16816(s[mt][nt],     qh[mt][ks], bl0, bl1);
                    mma16816(s[mt][nt + 1], qh[mt][ks], bh2, bh3);
                    mma16816(s[mt][nt + 1], ql[mt][ks], bh2, bh3);
                    mma16816(s[mt][nt + 1], qh[mt][ks], bl2, bl3);
                }
            }
        }

#pragma unroll
        for (int mt = 0; mt < 2; mt++) {
            const int tmin = qtile * BM + warp * 32 + mt * 16;
            const int grl0 = tmin + g;
            const int grl1 = grl0 + 8;
#pragma unroll
            for (int nt = 0; nt < 8; nt++)
#pragma unroll
                for (int e = 0; e < 4; e++) s[mt][nt][e] *= 0.125f;
            if (kb + BN - 1 > tmin) {
#pragma unroll
                for (int nt = 0; nt < 8; nt++) {
                    const int kg = kb + nt * 8 + qr * 2;
                    if (kg     > grl0) s[mt][nt][0] = -1e30f;
                    if (kg + 1 > grl0) s[mt][nt][1] = -1e30f;
                    if (kg     > grl1) s[mt][nt][2] = -1e30f;
                    if (kg + 1 > grl1) s[mt][nt][3] = -1e30f;
                }
            }

            float mx = -INFINITY;
#pragma unroll
            for (int nt = 0; nt < 8; nt++) {
                mx = fmaxf(mx, fmaxf(s[mt][nt][0], s[mt][nt][1]));
                mx = fmaxf(mx, fmaxf(s[mt][nt][2], s[mt][nt][3]));
            }
            mx = fmaxf(mx, __shfl_xor_sync(0xffffffffu, mx, 1));
            mx = fmaxf(mx, __shfl_xor_sync(0xffffffffu, mx, 2));

            const float mn = fmaxf(m[mt], mx);
            const float a  = __expf(m[mt] - mn);
            m[mt] = mn;

            float sum0 = 0.f, sum1 = 0.f;
#pragma unroll
            for (int nt = 0; nt < 8; nt++) {
                s[mt][nt][0] = __expf(s[mt][nt][0] - mn); sum0 += s[mt][nt][0];
                s[mt][nt][1] = __expf(s[mt][nt][1] - mn); sum0 += s[mt][nt][1];
                s[mt][nt][2] = __expf(s[mt][nt][2] - mn); sum1 += s[mt][nt][2];
                s[mt][nt][3] = __expf(s[mt][nt][3] - mn); sum1 += s[mt][nt][3];
            }
            sum0 += __shfl_xor_sync(0xffffffffu, sum0, 1);
            sum0 += __shfl_xor_sync(0xffffffffu, sum0, 2);
            sum1 += __shfl_xor_sync(0xffffffffu, sum1, 1);
            sum1 += __shfl_xor_sync(0xffffffffu, sum1, 2);
            l0[mt] = l0[mt] * a + sum0;
            l1[mt] = l1[mt] * a + sum1;

#pragma unroll
            for (int nd = 0; nd < 8; nd++) {
                o[mt][nd][0] *= a; o[mt][nd][1] *= a;
                o[mt][nd][2] *= a; o[mt][nd][3] *= a;
            }
        }

#pragma unroll
        for (int ks2 = 0; ks2 < 4; ks2++) {
            const int n2 = ks2 * 2;
            uint32_t pah[2][4], pal[2][4];
#pragma unroll
            for (int mt = 0; mt < 2; mt++) {
                split2(s[mt][n2][0],     s[mt][n2][1],     pah[mt][0], pal[mt][0]);
                split2(s[mt][n2][2],     s[mt][n2][3],     pah[mt][1], pal[mt][1]);
                split2(s[mt][n2 + 1][0], s[mt][n2 + 1][1], pah[mt][2], pal[mt][2]);
                split2(s[mt][n2 + 1][2], s[mt][n2 + 1][3], pah[mt][3], pal[mt][3]);
            }
#pragma unroll
            for (int ndp = 0; ndp < 4; ndp++) {
                const int nd = ndp * 2;
                const uint32_t off = (uint32_t)((ks2 * 16 * KPAD + nd * 8) * 2);
                uint32_t bh0, bh1, bh2, bh3, bl0, bl1, bl2, bl3;
                ldsm_x4_t(bh0, bh1, bh2, bh3, aVh + off);
                ldsm_x4_t(bl0, bl1, bl2, bl3, aVl + off);
#pragma unroll
                for (int mt = 0; mt < 2; mt++) {
                    mma16816(o[mt][nd],     pah[mt], bh0, bh1);
                    mma16816(o[mt][nd],     pal[mt], bh0, bh1);
                    mma16816(o[mt][nd],     pah[mt], bl0, bl1);
                    mma16816(o[mt][nd + 1], pah[mt], bh2, bh3);
                    mma16816(o[mt][nd + 1], pal[mt], bh2, bh3);
                    mma16816(o[mt][nd + 1], pah[mt], bl2, bl3);
                }
            }
        }
        __syncthreads();
    }

    float* ob = out + (size_t)b * SEQ * NSTATE + (size_t)h * DHEAD;
#pragma unroll
    for (int mt = 0; mt < 2; mt++) {
        const int r0 = rowA + mt * 16;
        const float inv0 = 1.f / l0[mt];
        const float inv1 = 1.f / l1[mt];
#pragma unroll
        for (int nd = 0; nd < 8; nd++) {
            const int dcol = nd * 8 + qr * 2;
            float2 v0; v0.x = o[mt][nd][0] * inv0; v0.y = o[mt][nd][1] * inv0;
            float2 v1; v1.x = o[mt][nd][2] * inv1; v1.y = o[mt][nd][3] * inv1;
            *reinterpret_cast<float2*>(ob + (size_t)r0 * NSTATE + dcol) = v0;
            *reinterpret_cast<float2*>(ob + (size_t)(r0 + 8) * NSTATE + dcol) = v1;
        }
    }
}

extern "C" void kernel_launch(void* const* d_in, const int* in_sizes, int n_in,
                              void* d_out, int out_size) {
    const float* x = (const float*)d_in[0];
    float* out = (float*)d_out;
    dim3 grid(SEQ / BM, NHEAD, BATCH);
    fa_kernel<<<grid, NTHREADS>>>(x, out);
}